// round 2
// baseline (speedup 1.0000x reference)
#include <cuda_runtime.h>
#include <math.h>

#define VV 32000
#define EE 1024
#define HH 1024
#define BB 8
#define TT 512
#define MTOK 4096   // B*T

#define RNN_NBLK 128

// ---------------- scratch (device globals; no allocation) ----------------
__device__ float g_xnorm[MTOK * EE];
__device__ float g_xp[MTOK * HH];
__device__ float g_h0[MTOK * HH];
__device__ float g_h1[MTOK * HH];
__device__ float g_act[MTOK * EE];

__device__ unsigned g_count = 0;
__device__ unsigned g_sense = 0;

// ---------------- LayerNorm(emb[x]) ----------------
__global__ void ln_embed_kernel(const int* __restrict__ x,
                                const float* __restrict__ emb,
                                float* __restrict__ out) {
    int r = blockIdx.x;                  // token index b*T+t
    int tid = threadIdx.x;               // 256 threads
    int row = x[r];
    const float4* src = (const float4*)(emb + (size_t)row * EE);
    float4 v = src[tid];
    float s = v.x + v.y + v.z + v.w;
    float q = v.x * v.x + v.y * v.y + v.z * v.z + v.w * v.w;
    #pragma unroll
    for (int off = 16; off > 0; off >>= 1) {
        s += __shfl_xor_sync(0xffffffffu, s, off);
        q += __shfl_xor_sync(0xffffffffu, q, off);
    }
    __shared__ float sh_s[8], sh_q[8];
    int warp = tid >> 5, lane = tid & 31;
    if (lane == 0) { sh_s[warp] = s; sh_q[warp] = q; }
    __syncthreads();
    __shared__ float s_mu, s_inv;
    if (tid == 0) {
        float S = 0.f, Q = 0.f;
        #pragma unroll
        for (int i = 0; i < 8; i++) { S += sh_s[i]; Q += sh_q[i]; }
        float mu = S * (1.0f / EE);
        float var = Q * (1.0f / EE) - mu * mu;
        s_mu = mu;
        s_inv = rsqrtf(var + 1e-5f);
    }
    __syncthreads();
    float mu = s_mu, inv = s_inv;
    float4 o;
    o.x = (v.x - mu) * inv; o.y = (v.y - mu) * inv;
    o.z = (v.z - mu) * inv; o.w = (v.w - mu) * inv;
    ((float4*)(out + (size_t)r * EE))[tid] = o;
}

// ---------------- SGEMM: C[M,N] = A[M,K] * B[N,K]^T (+bias, +relu) ----------------
// MODE 0: none; MODE 1: +bias; MODE 2: relu(+bias)
// BM=BN=128, BK=16, 256 threads, 8x8 microtile. All dims divisible.
template <int MODE>
__global__ void sgemm_tn_kernel(const float* __restrict__ A,
                                const float* __restrict__ B,
                                const float* __restrict__ bias,
                                float* __restrict__ C,
                                int M, int N, int K) {
    __shared__ float As[16][132];
    __shared__ float Bs[16][132];

    const int tid = threadIdx.x;
    const int m0 = blockIdx.x * 128;
    const int n0 = blockIdx.y * 128;
    const int tx = tid & 15;
    const int ty = tid >> 4;
    const int lr = tid >> 2;          // 0..63
    const int lk = (tid & 3) * 4;     // 0,4,8,12

    float c[8][8];
    #pragma unroll
    for (int i = 0; i < 8; i++)
        #pragma unroll
        for (int j = 0; j < 8; j++) c[i][j] = 0.f;

    for (int kt = 0; kt < K; kt += 16) {
        __syncthreads();
        float4 a0 = *(const float4*)&A[(size_t)(m0 + lr) * K + kt + lk];
        float4 a1 = *(const float4*)&A[(size_t)(m0 + lr + 64) * K + kt + lk];
        float4 b0 = *(const float4*)&B[(size_t)(n0 + lr) * K + kt + lk];
        float4 b1 = *(const float4*)&B[(size_t)(n0 + lr + 64) * K + kt + lk];
        As[lk + 0][lr] = a0.x; As[lk + 1][lr] = a0.y; As[lk + 2][lr] = a0.z; As[lk + 3][lr] = a0.w;
        As[lk + 0][lr + 64] = a1.x; As[lk + 1][lr + 64] = a1.y; As[lk + 2][lr + 64] = a1.z; As[lk + 3][lr + 64] = a1.w;
        Bs[lk + 0][lr] = b0.x; Bs[lk + 1][lr] = b0.y; Bs[lk + 2][lr] = b0.z; Bs[lk + 3][lr] = b0.w;
        Bs[lk + 0][lr + 64] = b1.x; Bs[lk + 1][lr + 64] = b1.y; Bs[lk + 2][lr + 64] = b1.z; Bs[lk + 3][lr + 64] = b1.w;
        __syncthreads();
        #pragma unroll
        for (int k = 0; k < 16; k++) {
            float4 aA = *(const float4*)&As[k][ty * 8];
            float4 aB = *(const float4*)&As[k][ty * 8 + 4];
            float4 bA = *(const float4*)&Bs[k][tx * 8];
            float4 bB = *(const float4*)&Bs[k][tx * 8 + 4];
            float a[8] = {aA.x, aA.y, aA.z, aA.w, aB.x, aB.y, aB.z, aB.w};
            float b[8] = {bA.x, bA.y, bA.z, bA.w, bB.x, bB.y, bB.z, bB.w};
            #pragma unroll
            for (int i = 0; i < 8; i++)
                #pragma unroll
                for (int j = 0; j < 8; j++)
                    c[i][j] = fmaf(a[i], b[j], c[i][j]);
        }
    }

    float bb0[8];
    if (MODE != 0) {
        float4 t0 = *(const float4*)&bias[n0 + tx * 8];
        float4 t1 = *(const float4*)&bias[n0 + tx * 8 + 4];
        bb0[0] = t0.x; bb0[1] = t0.y; bb0[2] = t0.z; bb0[3] = t0.w;
        bb0[4] = t1.x; bb0[5] = t1.y; bb0[6] = t1.z; bb0[7] = t1.w;
    }

    #pragma unroll
    for (int i = 0; i < 8; i++) {
        int row = m0 + ty * 8 + i;
        float o[8];
        #pragma unroll
        for (int j = 0; j < 8; j++) {
            float v = c[i][j];
            if (MODE != 0) v += bb0[j];
            if (MODE == 2) v = fmaxf(v, 0.f);
            o[j] = v;
        }
        float4 w0 = make_float4(o[0], o[1], o[2], o[3]);
        float4 w1 = make_float4(o[4], o[5], o[6], o[7]);
        *(float4*)&C[(size_t)row * N + n0 + tx * 8] = w0;
        *(float4*)&C[(size_t)row * N + n0 + tx * 8 + 4] = w1;
    }
}

// ---------------- Persistent RNN recurrence ----------------
// h_t = tanh(xp_t + W_hh h_{t-1} + b_hh), 512 sequential steps.
// 128 CTAs x 256 threads, each CTA owns 8 rows of W_hh (L1-resident).
__global__ void rnn_recurrence_kernel(const float* __restrict__ xp,
                                      const float* __restrict__ Whh,
                                      const float* __restrict__ bhh,
                                      float* __restrict__ hout) {
    __shared__ float h_s[BB][HH];       // 32 KB
    __shared__ float part[2][8][BB];

    const int tid = threadIdx.x;
    const int warp = tid >> 5, lane = tid & 31;
    const int rp = warp >> 1;           // row pair 0..3
    const int fh = warp & 1;            // feature half
    const int r0 = blockIdx.x * 8 + rp * 2;
    const float* w0p = Whh + (size_t)r0 * HH;
    const float* w1p = Whh + (size_t)(r0 + 1) * HH;

    unsigned sense = 0;                 // only thread 0 uses

    for (int t = 0; t < TT; t++) {
        // stage h_{t-1} into shared (zeros for t=0)
        #pragma unroll
        for (int i = 0; i < 8; i++) {
            int idx = tid + i * 256;            // 0..2047 float4s
            float4 v;
            if (t == 0) {
                v = make_float4(0.f, 0.f, 0.f, 0.f);
            } else {
                int b = idx >> 8, f4 = idx & 255;
                v = *(const float4*)&hout[((size_t)(b * TT + t - 1) << 10) + (f4 << 2)];
            }
            ((float4*)h_s)[idx] = v;
        }
        __syncthreads();

        float acc0[BB], acc1[BB];
        #pragma unroll
        for (int b = 0; b < BB; b++) { acc0[b] = 0.f; acc1[b] = 0.f; }
        #pragma unroll
        for (int it = 0; it < 4; it++) {
            int f = fh * 512 + it * 128 + lane * 4;
            float4 w0 = *(const float4*)&w0p[f];
            float4 w1 = *(const float4*)&w1p[f];
            #pragma unroll
            for (int b = 0; b < BB; b++) {
                float4 h4 = *(const float4*)&h_s[b][f];
                acc0[b] += w0.x * h4.x + w0.y * h4.y + w0.z * h4.z + w0.w * h4.w;
                acc1[b] += w1.x * h4.x + w1.y * h4.y + w1.z * h4.z + w1.w * h4.w;
            }
        }
        #pragma unroll
        for (int off = 16; off > 0; off >>= 1) {
            #pragma unroll
            for (int b = 0; b < BB; b++) {
                acc0[b] += __shfl_xor_sync(0xffffffffu, acc0[b], off);
                acc1[b] += __shfl_xor_sync(0xffffffffu, acc1[b], off);
            }
        }
        if (lane == 0) {
            #pragma unroll
            for (int b = 0; b < BB; b++) {
                part[fh][rp * 2][b] = acc0[b];
                part[fh][rp * 2 + 1][b] = acc1[b];
            }
        }
        __syncthreads();

        if (tid < 64) {
            int lrow = tid >> 3, b = tid & 7;
            int rg = blockIdx.x * 8 + lrow;
            float v = part[0][lrow][b] + part[1][lrow][b]
                    + xp[((size_t)(b * TT + t) << 10) + rg] + bhh[rg];
            hout[((size_t)(b * TT + t) << 10) + rg] = tanhf(v);
        }
        __threadfence();

        // grid barrier (sense reversal; 128 co-resident CTAs)
        __syncthreads();
        if (tid == 0) {
            sense ^= 1u;
            if (atomicAdd(&g_count, 1u) == RNN_NBLK - 1) {
                atomicExch(&g_count, 0u);
                __threadfence();
                *(volatile unsigned*)&g_sense = sense;
            } else {
                while (*(volatile unsigned*)&g_sense != sense) { }
                __threadfence();
            }
        }
        __syncthreads();
    }
}

// ---------------- launch ----------------
extern "C" void kernel_launch(void* const* d_in, const int* in_sizes, int n_in,
                              void* d_out, int out_size) {
    const int*   x      = (const int*)d_in[0];
    const float* emb    = (const float*)d_in[1];
    const float* W_ih0  = (const float*)d_in[2];
    const float* W_hh0  = (const float*)d_in[3];
    const float* b_ih0  = (const float*)d_in[4];
    const float* b_hh0  = (const float*)d_in[5];
    const float* W_ih1  = (const float*)d_in[6];
    const float* W_hh1  = (const float*)d_in[7];
    const float* b_ih1  = (const float*)d_in[8];
    const float* b_hh1  = (const float*)d_in[9];
    const float* W_lin  = (const float*)d_in[10];
    const float* b_lin  = (const float*)d_in[11];
    float* out = (float*)d_out;

    float *xnorm, *xp, *h0, *h1, *act;
    cudaGetSymbolAddress((void**)&xnorm, g_xnorm);
    cudaGetSymbolAddress((void**)&xp,    g_xp);
    cudaGetSymbolAddress((void**)&h0,    g_h0);
    cudaGetSymbolAddress((void**)&h1,    g_h1);
    cudaGetSymbolAddress((void**)&act,   g_act);

    // 1. xnorm = LN(emb[x])
    ln_embed_kernel<<<MTOK, 256>>>(x, emb, xnorm);

    // 2. xp = xnorm @ W_ih0^T + b_ih0
    {
        dim3 grid(MTOK / 128, HH / 128);
        sgemm_tn_kernel<1><<<grid, 256>>>(xnorm, W_ih0, b_ih0, xp, MTOK, HH, EE);
    }

    // 3. layer 0 recurrence
    rnn_recurrence_kernel<<<RNN_NBLK, 256>>>(xp, W_hh0, b_hh0, h0);

    // 4. xp = h0 @ W_ih1^T + b_ih1
    {
        dim3 grid(MTOK / 128, HH / 128);
        sgemm_tn_kernel<1><<<grid, 256>>>(h0, W_ih1, b_ih1, xp, MTOK, HH, HH);
    }

    // 5. layer 1 recurrence
    rnn_recurrence_kernel<<<RNN_NBLK, 256>>>(xp, W_hh1, b_hh1, h1);

    // 6. act = relu(h1 @ W_lin^T + b_lin)
    {
        dim3 grid(MTOK / 128, EE / 128);
        sgemm_tn_kernel<2><<<grid, 256>>>(h1, W_lin, b_lin, act, MTOK, EE, HH);
    }

    // 7. out = act @ emb^T   [4096, 32000]
    {
        dim3 grid(MTOK / 128, VV / 128);
        sgemm_tn_kernel<0><<<grid, 256>>>(act, emb, nullptr, out, MTOK, VV, EE);
    }
}